// round 6
// baseline (speedup 1.0000x reference)
#include <cuda_runtime.h>
#include <cuda_fp16.h>
#include <cstdint>

#define BATCH 256
#define N_GENES 8192
#define WM 4
#define HID (N_GENES * WM)       // 32768
#define N_TF 1024
#define GPT 64
#define EDGES3 (GPT * WM)        // 256
#define EPS 1e-5f
#define GENES_PER_BLOCK 8

// Scratch: layer-2 output stored TRANSPOSED in fp16: hT[col * BATCH + b]
__device__ __half g_hT[HID * BATCH];

__device__ __forceinline__ float2 warp_sum2(float2 v) {
#pragma unroll
    for (int o = 16; o; o >>= 1) {
        v.x += __shfl_xor_sync(0xffffffffu, v.x, o);
        v.y += __shfl_xor_sync(0xffffffffu, v.y, o);
    }
    return v;
}

struct __align__(8) H22 { __half2 a, b; };

// Fused: layer1 -> relu -> BN -> layer2 -> relu -> BN. One warp per gene.
// Lane owns batches {4L..4L+3} and {128+4L..128+4L+3} (k=0,1; p=0..3).
// BN1 scale/shift folded into layer2 weights (exact algebra).
__global__ __launch_bounds__(256) void k_layers12(
    const float* __restrict__ x,    // [BATCH, N_GENES] row-major
    const float* __restrict__ w1, const float* __restrict__ b1,
    const float* __restrict__ w2, const float* __restrict__ b2)
{
    __shared__ float sxT[GENES_PER_BLOCK][260];   // pad 260: float4-aligned, conflict-free

    const int g0 = blockIdx.x * GENES_PER_BLOCK;
    const int t = threadIdx.x;
    const int warp = t >> 5;
    const int lane = t & 31;

    // Tile load: thread t = batch row t, 8 genes via 2x LDG.128.
    {
        const float4* xr = reinterpret_cast<const float4*>(x + (size_t)t * N_GENES + g0);
        float4 a = xr[0], b = xr[1];
        sxT[0][t] = a.x; sxT[1][t] = a.y; sxT[2][t] = a.z; sxT[3][t] = a.w;
        sxT[4][t] = b.x; sxT[5][t] = b.y; sxT[6][t] = b.z; sxT[7][t] = b.w;
    }
    __syncthreads();

    const int gi = warp;           // one gene per warp
    const int g = g0 + gi;

    float w1v[4], b1v[4], b2v[4], w2v[16];
#pragma unroll
    for (int j = 0; j < 4; j++) {
        w1v[j] = w1[4 * g + j];
        b1v[j] = b1[4 * g + j];
        b2v[j] = b2[4 * g + j];
    }
#pragma unroll
    for (int e = 0; e < 16; e++) w2v[e] = w2[16 * g + e];

    // layer1 + relu (raw, pre-BN)
    float h1[2][4][4];             // [k][p][j]
#pragma unroll
    for (int k = 0; k < 2; k++) {
        float4 xv = *reinterpret_cast<const float4*>(&sxT[gi][128 * k + 4 * lane]);
        float xs[4] = {xv.x, xv.y, xv.z, xv.w};
#pragma unroll
        for (int p = 0; p < 4; p++)
#pragma unroll
            for (int j = 0; j < 4; j++)
                h1[k][p][j] = fmaxf(fmaf(w1v[j], xs[p], b1v[j]), 0.0f);
    }

    // BN1 stats per column j (single pass), fold into layer2 weights
    float m1[4], inv1[4];
#pragma unroll
    for (int j = 0; j < 4; j++) {
        float2 ss = make_float2(0.f, 0.f);
#pragma unroll
        for (int k = 0; k < 2; k++)
#pragma unroll
            for (int p = 0; p < 4; p++) {
                float h = h1[k][p][j];
                ss.x += h; ss.y += h * h;
            }
        ss = warp_sum2(ss);
        float m = ss.x * (1.0f / BATCH);
        float var = fmaxf(ss.y * (1.0f / BATCH) - m * m, 0.0f);
        m1[j] = m;
        inv1[j] = rsqrtf(var + EPS);
    }
    float w2f[16], b2f[4];
#pragma unroll
    for (int i = 0; i < 4; i++) {
        float bb = b2v[i];
#pragma unroll
        for (int j = 0; j < 4; j++) {
            float wf = w2v[4 * i + j] * inv1[j];
            w2f[4 * i + j] = wf;
            bb -= wf * m1[j];
        }
        b2f[i] = bb;
    }

    // layer2 + relu on raw h1
    float h2[2][4][4];             // [k][p][i]
#pragma unroll
    for (int k = 0; k < 2; k++)
#pragma unroll
        for (int p = 0; p < 4; p++)
#pragma unroll
            for (int i = 0; i < 4; i++) {
                float acc = b2f[i];
#pragma unroll
                for (int j = 0; j < 4; j++) acc = fmaf(w2f[4 * i + j], h1[k][p][j], acc);
                h2[k][p][i] = fmaxf(acc, 0.0f);
            }

    // BN2 per column i, transposed ST.64 half2 store
#pragma unroll
    for (int i = 0; i < 4; i++) {
        float2 ss = make_float2(0.f, 0.f);
#pragma unroll
        for (int k = 0; k < 2; k++)
#pragma unroll
            for (int p = 0; p < 4; p++) {
                float h = h2[k][p][i];
                ss.x += h; ss.y += h * h;
            }
        ss = warp_sum2(ss);
        float m = ss.x * (1.0f / BATCH);
        float var = fmaxf(ss.y * (1.0f / BATCH) - m * m, 0.0f);
        float inv = rsqrtf(var + EPS);

        __half2* dst = reinterpret_cast<__half2*>(&g_hT[(4 * g + i) * BATCH]);
#pragma unroll
        for (int k = 0; k < 2; k++) {
            H22 hv;
            hv.a = __floats2half2_rn((h2[k][0][i] - m) * inv, (h2[k][1][i] - m) * inv);
            hv.b = __floats2half2_rn((h2[k][2][i] - m) * inv, (h2[k][3][i] - m) * inv);
            *reinterpret_cast<H22*>(&dst[64 * k + 2 * lane]) = hv;
        }
    }
}

// layer3: one block (8 warps) per TF; warp handles 32 edges, lane covers
// batches 8*lane..8*lane+7 via one LDG.128 per edge. Products accumulated in
// half2 (HFMA2), widened to fp32 every 4 edges. Cross-warp combine in smem.
struct __align__(8) WC { __half2 w2; int boff; };

__global__ __launch_bounds__(256, 8) void k_layer3(
    const float* __restrict__ w3, const float* __restrict__ b3,
    const int* __restrict__ cols3,
    float* __restrict__ out)   // [BATCH, N_TF]
{
    const int tf = blockIdx.x;
    const int t = threadIdx.x;        // 0..255
    const int warp = t >> 5;
    const int lane = t & 31;

    __shared__ WC swc[EDGES3];
    __shared__ float sacc[8][BATCH];      // 8 KB
    __shared__ float2 sred[8];

    swc[t].w2   = __half2half2(__float2half_rn(w3[tf * EDGES3 + t]));
    swc[t].boff = cols3[tf * EDGES3 + t] * (BATCH * 2);   // bytes
    __syncthreads();

    const char* hbase = reinterpret_cast<const char*>(g_hT) + lane * 16;

    float acc[8];
#pragma unroll
    for (int s = 0; s < 8; s++) acc[s] = 0.f;

    const __half2 hz = __float2half2_rn(0.f);
#pragma unroll
    for (int c = 0; c < 8; c++) {          // 8 chunks x 4 edges
        __half2 p0 = hz, p1 = hz, p2 = hz, p3 = hz;
#pragma unroll
        for (int j = 0; j < 4; j++) {
            WC a = swc[warp * 32 + c * 4 + j];
            uint4 v = *reinterpret_cast<const uint4*>(hbase + a.boff);
            p0 = __hfma2(a.w2, *reinterpret_cast<__half2*>(&v.x), p0);
            p1 = __hfma2(a.w2, *reinterpret_cast<__half2*>(&v.y), p1);
            p2 = __hfma2(a.w2, *reinterpret_cast<__half2*>(&v.z), p2);
            p3 = __hfma2(a.w2, *reinterpret_cast<__half2*>(&v.w), p3);
        }
        float2 f0 = __half22float2(p0);
        float2 f1 = __half22float2(p1);
        float2 f2 = __half22float2(p2);
        float2 f3 = __half22float2(p3);
        acc[0] += f0.x; acc[1] += f0.y;
        acc[2] += f1.x; acc[3] += f1.y;
        acc[4] += f2.x; acc[5] += f2.y;
        acc[6] += f3.x; acc[7] += f3.y;
    }

    // Park partials: warp's acc[s] is batch 8*lane+s
    *reinterpret_cast<float4*>(&sacc[warp][8 * lane])     = make_float4(acc[0], acc[1], acc[2], acc[3]);
    *reinterpret_cast<float4*>(&sacc[warp][8 * lane + 4]) = make_float4(acc[4], acc[5], acc[6], acc[7]);
    __syncthreads();

    // Thread t owns batch b = t: sum over the 8 warps' partials.
    float z = b3[tf];
#pragma unroll
    for (int w = 0; w < 8; w++) z += sacc[w][t];

    // Single-pass BN over the 256 batch values.
    float2 ss = warp_sum2(make_float2(z, z * z));
    if (lane == 0) sred[warp] = ss;
    __syncthreads();
    float S = 0.f, S2 = 0.f;
#pragma unroll
    for (int i = 0; i < 8; i++) { S += sred[i].x; S2 += sred[i].y; }
    float m = S * (1.0f / BATCH);
    float var = fmaxf(S2 * (1.0f / BATCH) - m * m, 0.0f);
    float inv = rsqrtf(var + EPS);

    out[t * N_TF + tf] = (z - m) * inv;
}

extern "C" void kernel_launch(void* const* d_in, const int* in_sizes, int n_in,
                              void* d_out, int out_size)
{
    const float* x  = (const float*)d_in[0];
    const float* w1 = (const float*)d_in[1];
    const float* b1 = (const float*)d_in[2];
    const float* w2 = (const float*)d_in[3];
    const float* b2 = (const float*)d_in[4];
    const float* w3 = (const float*)d_in[5];
    const float* b3 = (const float*)d_in[6];
    const int* cols3 = (const int*)d_in[12];
    float* out = (float*)d_out;

    k_layers12<<<N_GENES / GENES_PER_BLOCK, 256>>>(x, w1, b1, w2, b2);
    k_layer3<<<N_TF, 256>>>(w3, b3, cols3, out);
}